// round 14
// baseline (speedup 1.0000x reference)
#include <cuda_runtime.h>
#include <cuda_bf16.h>
#include <math.h>
#include <float.h>
#include <stdint.h>

#define HID 1536
#define NH  8
#define HD  192
#define WW  12
#define CC  24
#define FF  13
#define MAXPAST 12

#define BM 128
#define BN 64
#define BK 64
#define NCHUNK (HID / BK)     // 24
#define STG_BYTES 49152       // Ahi 16K | Alo 16K | Bhi 8K | Blo 8K
#define NSTAGE 2
#define KSTR 196              // HD+4: 16B-aligned, 3-phase (floor) QK float4 loads

// attn grouping: 3 query-blocks per CTA
#define UG    3
#define QROWS (UG * WW)       // 36
#define CROWS (QROWS + MAXPAST) // 48 context rows (windows overlap)

// ---------------- device scratch (no-alloc rule) ----------------
__device__ __align__(128) float g_q[25165824];
__device__ __align__(128) float g_k[25165824];
__device__ __align__(128) float g_v[25165824];
__device__ __align__(128) float g_sin[FF * HID];
__device__ __align__(128) __nv_bfloat16 g_ahi[25165824];
__device__ __align__(128) __nv_bfloat16 g_alo[25165824];
__device__ __align__(128) __nv_bfloat16 g_whi[3 * 2359296];
__device__ __align__(128) __nv_bfloat16 g_wlo[3 * 2359296];

// ---------------- PTX helpers (baseline PTX only) ----------------
__device__ __forceinline__ uint32_t smem_u32(const void* p) {
    uint32_t a;
    asm("{ .reg .u64 t; cvta.to.shared.u64 t, %1; cvt.u32.u64 %0, t; }" : "=r"(a) : "l"(p));
    return a;
}
#define SWZ128(o) ((o) ^ (((o) >> 3) & 0x70))

#define CP_ASYNC16(dst, src) \
    asm volatile("cp.async.cg.shared.global [%0], [%1], 16;" :: "r"(dst), "l"(src))
#define CP_COMMIT()  asm volatile("cp.async.commit_group;")
#define CP_WAIT0()   asm volatile("cp.async.wait_group 0;" ::: "memory")

__device__ __forceinline__ void ldsm4(uint32_t addr, uint32_t* r) {
    asm volatile("ldmatrix.sync.aligned.m8n8.x4.shared.b16 {%0,%1,%2,%3}, [%4];"
                 : "=r"(r[0]), "=r"(r[1]), "=r"(r[2]), "=r"(r[3]) : "r"(addr));
}
__device__ __forceinline__ void mma16816(float* d, const uint32_t* a, const uint32_t* b) {
    asm volatile(
        "mma.sync.aligned.m16n8k16.row.col.f32.bf16.bf16.f32 "
        "{%0,%1,%2,%3}, {%4,%5,%6,%7}, {%8,%9}, {%0,%1,%2,%3};"
        : "+f"(d[0]), "+f"(d[1]), "+f"(d[2]), "+f"(d[3])
        : "r"(a[0]), "r"(a[1]), "r"(a[2]), "r"(a[3]), "r"(b[0]), "r"(b[1]));
}

// ---------------- conversion kernels ----------------
__global__ __launch_bounds__(256) void convA(const float* __restrict__ A) {
    int idx = (blockIdx.x * 256 + threadIdx.x) * 4;
    float4 v = *(const float4*)(A + idx);
    __nv_bfloat16 h[4], l[4];
    float x[4] = {v.x, v.y, v.z, v.w};
    #pragma unroll
    for (int i = 0; i < 4; i++) {
        h[i] = __float2bfloat16(x[i]);
        l[i] = __float2bfloat16(x[i] - __bfloat162float(h[i]));
    }
    *(uint2*)(g_ahi + idx) = *(uint2*)h;
    *(uint2*)(g_alo + idx) = *(uint2*)l;
}

// transpose W [K x N] -> hi/lo [N x K] bf16
__global__ __launch_bounds__(256) void convW(const float* __restrict__ W0,
                                             const float* __restrict__ W1,
                                             const float* __restrict__ W2) {
    __shared__ float ts[32][33];
    const int mat = blockIdx.z;
    const float* Wm = (mat == 0) ? W0 : (mat == 1) ? W1 : W2;
    const int n0 = blockIdx.x * 32, k0 = blockIdx.y * 32;
    const int tx = threadIdx.x & 31, ty = threadIdx.x >> 5;  // 32 x 8
    #pragma unroll
    for (int i = 0; i < 4; i++)
        ts[ty + i * 8][tx] = Wm[(size_t)(k0 + ty + i * 8) * HID + n0 + tx];
    __syncthreads();
    size_t base = (size_t)mat * 2359296;
    #pragma unroll
    for (int i = 0; i < 4; i++) {
        int n = n0 + ty + i * 8, k = k0 + tx;
        float x = ts[tx][ty + i * 8];
        __nv_bfloat16 h = __float2bfloat16(x);
        __nv_bfloat16 l = __float2bfloat16(x - __bfloat162float(h));
        g_whi[base + (size_t)n * HID + k] = h;
        g_wlo[base + (size_t)n * HID + k] = l;
    }
}

// ---------------- HMMA bf16 3-pass GEMM (128x64 tile, 2 CTA/SM) ------------
__device__ __forceinline__ void load_chunk(
    uint32_t sbase, const __nv_bfloat16* Ah, const __nv_bfloat16* Al,
    const __nv_bfloat16* Bh, const __nv_bfloat16* Bl, int t, int tid)
{
    const int kof = t * BK;
    #pragma unroll
    for (int i = 0; i < 4; i++) {           // A: 128 rows x 8 x 16B
        int l = tid + i * 256;
        int row = l >> 3, c16 = l & 7;
        uint32_t so = SWZ128((uint32_t)(row * 128 + c16 * 16));
        size_t go = (size_t)row * HID + kof + c16 * 8;
        CP_ASYNC16(sbase + so,         Ah + go);
        CP_ASYNC16(sbase + 16384 + so, Al + go);
    }
    #pragma unroll
    for (int i = 0; i < 2; i++) {           // B: 64 rows x 8 x 16B
        int l = tid + i * 256;
        int row = l >> 3, c16 = l & 7;
        uint32_t so = SWZ128((uint32_t)(row * 128 + c16 * 16));
        size_t go = (size_t)row * HID + kof + c16 * 8;
        CP_ASYNC16(sbase + 32768 + so, Bh + go);
        CP_ASYNC16(sbase + 40960 + so, Bl + go);
    }
}

__global__ __launch_bounds__(256, 2) void qkv_mma() {
    extern __shared__ char smem[];
    const uint32_t sb = smem_u32(smem);
    const int tid = threadIdx.x, wid = tid >> 5, lid = tid & 31;
    const int wm = wid >> 1, wn = wid & 1;           // 4m x 2n, warp tile 32x32
    const int nt = blockIdx.x, mt = blockIdx.y, mat = blockIdx.z;

    const __nv_bfloat16* Ah = g_ahi + (size_t)mt * BM * HID;
    const __nv_bfloat16* Al = g_alo + (size_t)mt * BM * HID;
    const __nv_bfloat16* Bh = g_whi + (size_t)mat * 2359296 + (size_t)nt * BN * HID;
    const __nv_bfloat16* Bl = g_wlo + (size_t)mat * 2359296 + (size_t)nt * BN * HID;
    float* O = (mat == 0) ? g_q : (mat == 1) ? g_k : g_v;

    float acc[2][4][4];
    #pragma unroll
    for (int i = 0; i < 2; i++)
        #pragma unroll
        for (int j = 0; j < 4; j++)
            #pragma unroll
            for (int r = 0; r < 4; r++) acc[i][j][r] = 0.f;

    const int q = lid >> 3, r8 = lid & 7;
    const int a_row = wm * 32 + ((q & 1) << 3) + r8;
    const int a_kb  = (q >> 1) << 4;
    const int b_rowbase = wn * 32 + ((q >> 1) << 3) + r8;
    const int b_kb  = (q & 1) << 4;

    load_chunk(sb, Ah, Al, Bh, Bl, 0, tid); CP_COMMIT();

    for (int t = 0; t < NCHUNK; ++t) {
        CP_WAIT0();
        __syncthreads();
        if (t + 1 < NCHUNK) {
            load_chunk(sb + ((t + 1) & 1) * STG_BYTES, Ah, Al, Bh, Bl, t + 1, tid);
            CP_COMMIT();
        }
        const uint32_t stg = sb + (t & 1) * STG_BYTES;

        #pragma unroll
        for (int ks = 0; ks < 4; ++ks) {
            uint32_t ahi[2][4], alo[2][4];
            #pragma unroll
            for (int i = 0; i < 2; i++) {
                uint32_t off = SWZ128((uint32_t)((a_row + i * 16) * 128 + ks * 32 + a_kb));
                ldsm4(stg + off,         ahi[i]);
                ldsm4(stg + 16384 + off, alo[i]);
            }
            #pragma unroll
            for (int p = 0; p < 2; p++) {
                uint32_t bh[4], bl[4];
                uint32_t off = SWZ128((uint32_t)((b_rowbase + p * 16) * 128 + ks * 32 + b_kb));
                ldsm4(stg + 32768 + off, bh);
                ldsm4(stg + 40960 + off, bl);
                #pragma unroll
                for (int i = 0; i < 2; i++) {
                    mma16816(acc[i][2 * p],     ahi[i], bh);
                    mma16816(acc[i][2 * p],     alo[i], bh);
                    mma16816(acc[i][2 * p],     ahi[i], bl);
                    mma16816(acc[i][2 * p + 1], ahi[i], bh + 2);
                    mma16816(acc[i][2 * p + 1], alo[i], bh + 2);
                    mma16816(acc[i][2 * p + 1], ahi[i], bl + 2);
                }
            }
        }
    }

    const int orow0 = mt * BM + wm * 32 + (lid >> 2);
    const int ocol0 = nt * BN + wn * 32 + (lid & 3) * 2;
    #pragma unroll
    for (int i = 0; i < 2; i++) {
        #pragma unroll
        for (int j = 0; j < 4; j++) {
            float* p0 = O + (size_t)(orow0 + i * 16)     * HID + ocol0 + j * 8;
            float* p1 = O + (size_t)(orow0 + i * 16 + 8) * HID + ocol0 + j * 8;
            *(float2*)p0 = make_float2(acc[i][j][0], acc[i][j][1]);
            *(float2*)p1 = make_float2(acc[i][j][2], acc[i][j][3]);
        }
    }
}

// ---------------- sin embedding ----------------
__global__ void sinemb_kernel(const float* __restrict__ wpos) {
    const int f = blockIdx.y;
    const int n = blockIdx.x * 256 + threadIdx.x;
    const float p = (float)(MAXPAST - f);
    const float linc = 9.210340371976184f / 767.0f;
    float acc = 0.f;
    for (int i = 0; i < 768; i++) {
        float inv = expf(-linc * (float)i);
        float s = p * inv;
        acc += sinf(s) * wpos[(size_t)i * HID + n];
        acc += cosf(s) * wpos[(size_t)(i + 768) * HID + n];
    }
    g_sin[f * HID + n] = acc;
}

// ---------------- attention: 3 query-blocks per CTA ----------------
// smem (dynamic): qs[36*192] ks[48*196] vs[48*192] lg[864] ssc[192] sval[48]
#define ATTN_SMEM ((QROWS * HD + CROWS * KSTR + CROWS * HD + UG * WW * CC + HD) * 4 + CROWS * 4)

__global__ __launch_bounds__(256) void attn_kernel(
    const unsigned char* __restrict__ mask,
    const float* __restrict__ pds,
    float* __restrict__ out, int T)
{
    extern __shared__ float sm[];
    float* qs  = sm;                       // 36*192
    float* ks  = qs + QROWS * HD;          // 48*196
    float* vs  = ks + CROWS * KSTR;        // 48*192
    float* lg  = vs + CROWS * HD;          // 864
    float* ssc = lg + UG * WW * CC;        // 192
    int*   sval = (int*)(ssc + HD);        // 48

    const int ug = blockIdx.x, h = blockIdx.y, b = blockIdx.z;
    const int tid = threadIdx.x;
    const int base = ug * QROWS - MAXPAST;   // first context row (global t)

    if (tid < HD) {
        const float qsc = 0.0721687836487032f / 0.693147180559945f;
        ssc[tid] = qsc * log1pf(expf(pds[tid]));
    }
    if (tid >= HD && tid < HD + CROWS) {
        int j = tid - HD;
        int tk = base + j;
        sval[j] = (tk >= 0 && tk < T && mask[(size_t)b * T + tk] == 0);
    }
    __syncthreads();

    // q rows: t = ug*36 + r
    for (int i = tid; i < QROWS * (HD / 4); i += 256) {
        int r = i / (HD / 4), dd = i - r * (HD / 4);
        int t = ug * QROWS + r;
        float4 v = make_float4(0.f, 0.f, 0.f, 0.f);
        if (t < T) {
            float4 g = *(const float4*)&g_q[((size_t)b * T + t) * HID + h * HD + dd * 4];
            v = make_float4(g.x * ssc[dd * 4], g.y * ssc[dd * 4 + 1],
                            g.z * ssc[dd * 4 + 2], g.w * ssc[dd * 4 + 3]);
        }
        *(float4*)&qs[r * HD + dd * 4] = v;
    }
    // k/v context rows: t = base + r, r in [0,48)
    for (int i = tid; i < CROWS * (HD / 4); i += 256) {
        int r = i / (HD / 4), dd = i - r * (HD / 4);
        int t = base + r;
        float4 kv = make_float4(0.f, 0.f, 0.f, 0.f);
        float4 vv = make_float4(0.f, 0.f, 0.f, 0.f);
        if (t >= 0 && t < T) {
            size_t off = ((size_t)b * T + t) * HID + h * HD + dd * 4;
            kv = *(const float4*)&g_k[off];
            vv = *(const float4*)&g_v[off];
        }
        *(float4*)&ks[r * KSTR + dd * 4] = kv;
        *(float4*)&vs[r * HD + dd * 4]  = vv;
    }
    __syncthreads();

    // content logits: 864 items. k row for (ui, c) = ui*12 + c  (0..47)
    for (int idx = tid; idx < UG * WW * CC; idx += 256) {
        int ui = idx / (WW * CC), rem = idx - ui * (WW * CC);
        int w = rem / CC, c = rem - w * CC;
        const float4* qp = (const float4*)(qs + (ui * WW + w) * HD);
        const float4* kp = (const float4*)(ks + (ui * WW + c) * KSTR);
        float4 a4 = make_float4(0.f, 0.f, 0.f, 0.f);
        #pragma unroll 8
        for (int d = 0; d < HD / 4; d++) {
            float4 qv = qp[d], kv = kp[d];
            a4.x = fmaf(qv.x, kv.x, a4.x);
            a4.y = fmaf(qv.y, kv.y, a4.y);
            a4.z = fmaf(qv.z, kv.z, a4.z);
            a4.w = fmaf(qv.w, kv.w, a4.w);
        }
        lg[idx] = (a4.x + a4.y) + (a4.z + a4.w);
    }
    __syncthreads();

    // position logits (shifted c = w + f): 468 items
    for (int idx = tid; idx < UG * WW * FF; idx += 256) {
        int ui = idx / (WW * FF), rem = idx - ui * (WW * FF);
        int w = rem / FF, f = rem - w * FF;
        const float4* qp = (const float4*)(qs + (ui * WW + w) * HD);
        const float4* sp = (const float4*)(g_sin + (size_t)f * HID + h * HD);
        float4 a4 = make_float4(0.f, 0.f, 0.f, 0.f);
        #pragma unroll 8
        for (int d = 0; d < HD / 4; d++) {
            float4 qv = qp[d], sv = sp[d];
            a4.x = fmaf(qv.x, sv.x, a4.x);
            a4.y = fmaf(qv.y, sv.y, a4.y);
            a4.z = fmaf(qv.z, sv.z, a4.z);
            a4.w = fmaf(qv.w, sv.w, a4.w);
        }
        lg[ui * WW * CC + w * CC + w + f] += (a4.x + a4.y) + (a4.z + a4.w);
    }
    __syncthreads();

    // tanh cap + mask: 864 parallel
    for (int idx = tid; idx < UG * WW * CC; idx += 256) {
        int ui = idx / (WW * CC), rem = idx - ui * (WW * CC);
        int w = rem / CC, c = rem - w * CC;
        float lv = tanhf(lg[idx] * (1.f / 50.f)) * 50.f;
        bool ok = sval[ui * WW + c] && (c >= w) && (c <= w + MAXPAST);
        lg[idx] = ok ? lv : -FLT_MAX;
    }
    __syncthreads();

    // softmax: 36 rows, one thread each
    if (tid < UG * WW) {
        float row[CC];
        float mx = -FLT_MAX;
        #pragma unroll
        for (int c = 0; c < CC; c++) {
            row[c] = lg[tid * CC + c];
            if (row[c] > mx) mx = row[c];
        }
        float s = 0.f;
        #pragma unroll
        for (int c = 0; c < CC; c++) {
            float e = (row[c] == -FLT_MAX) ? 0.f : expf(row[c] - mx);
            row[c] = e; s += e;
        }
        float inv = 1.f / s;
        #pragma unroll
        for (int c = 0; c < CC; c++) lg[tid * CC + c] = row[c] * inv;
    }
    __syncthreads();

    // ctx = probs @ V: 1728 items. v row for (r, c) = (r/12)*12 + c
    for (int i = tid; i < QROWS * (HD / 4); i += 256) {
        int r = i / (HD / 4), dd = i - r * (HD / 4);
        int t = ug * QROWS + r;
        if (t < T) {
            const float* pp = lg + r * CC;
            const int vbase = (r / WW) * WW;
            float4 a = make_float4(0.f, 0.f, 0.f, 0.f);
            #pragma unroll
            for (int c = 0; c < CC; c++) {
                float p = pp[c];
                const float* vp = &vs[(vbase + c) * HD + dd * 4];
                a.x = fmaf(p, vp[0], a.x);
                a.y = fmaf(p, vp[1], a.y);
                a.z = fmaf(p, vp[2], a.z);
                a.w = fmaf(p, vp[3], a.w);
            }
            *(float4*)&out[((size_t)b * T + t) * HID + h * HD + dd * 4] = a;
        }
    }
}

// ---------------------------------------------------------------------------
extern "C" void kernel_launch(void* const* d_in, const int* in_sizes, int n_in,
                              void* d_out, int out_size)
{
    const float*         hs   = (const float*)d_in[0];
    const unsigned char* mask = (const unsigned char*)d_in[1];
    const float*         wq   = (const float*)d_in[2];
    const float*         wk   = (const float*)d_in[3];
    const float*         wv   = (const float*)d_in[4];
    const float*         wpos = (const float*)d_in[5];
    const float*         pds  = (const float*)d_in[6];

    const int M  = in_sizes[0] / HID;   // 16384
    const int T  = 4096;
    const int Bq = M / T;
    const int U  = (T + WW - 1) / WW;   // 342
    const int UGRID = U / UG;           // 114 (342 = 3*114 exactly)

    static int smem_set = 0;
    const int dynsmem = NSTAGE * STG_BYTES;  // 98304
    if (!smem_set) {
        cudaFuncSetAttribute(qkv_mma, cudaFuncAttributeMaxDynamicSharedMemorySize, dynsmem);
        cudaFuncSetAttribute(attn_kernel, cudaFuncAttributeMaxDynamicSharedMemorySize, ATTN_SMEM);
        smem_set = 1;
    }

    convA<<<M * HID / 1024, 256>>>(hs);
    convW<<<dim3(HID / 32, HID / 32, 3), 256>>>(wq, wk, wv);
    sinemb_kernel<<<dim3(HID / 256, FF), 256>>>(wpos);
    qkv_mma<<<dim3(HID / BN, M / BM, 3), 256, dynsmem>>>();
    attn_kernel<<<dim3(UGRID, NH, Bq), 256, ATTN_SMEM>>>(mask, pds, (float*)d_out, T);
}

// round 15
// speedup vs baseline: 1.5983x; 1.5983x over previous
#include <cuda_runtime.h>
#include <cuda_fp16.h>
#include <math.h>
#include <float.h>
#include <stdint.h>

#define HID 1536
#define NH  8
#define HD  192
#define WW  12
#define CC  24
#define FF  13
#define MAXPAST 12

#define BM 128
#define BN 64
#define BK 64
#define NCHUNK (HID / BK)     // 24
#define STG_BYTES 40960       // Ahi 16K | Alo 16K | B 8K
#define NSTAGE 2
#define KSTR 196              // HD+4: 16B-aligned, crossbar-floor QK float4 loads

// ---------------- device scratch (no-alloc rule) ----------------
__device__ __align__(128) float g_q[25165824];
__device__ __align__(128) float g_k[25165824];
__device__ __align__(128) float g_v[25165824];
__device__ __align__(128) float g_sin[FF * HID];
__device__ __align__(128) __half g_ahi[25165824];
__device__ __align__(128) __half g_alo[25165824];
__device__ __align__(128) __half g_wf[3 * 2359296];

// ---------------- PTX helpers (baseline PTX only) ----------------
__device__ __forceinline__ uint32_t smem_u32(const void* p) {
    uint32_t a;
    asm("{ .reg .u64 t; cvta.to.shared.u64 t, %1; cvt.u32.u64 %0, t; }" : "=r"(a) : "l"(p));
    return a;
}
#define SWZ128(o) ((o) ^ (((o) >> 3) & 0x70))

#define CP_ASYNC16(dst, src) \
    asm volatile("cp.async.cg.shared.global [%0], [%1], 16;" :: "r"(dst), "l"(src))
#define CP_COMMIT()  asm volatile("cp.async.commit_group;")
#define CP_WAIT0()   asm volatile("cp.async.wait_group 0;" ::: "memory")

__device__ __forceinline__ void ldsm4(uint32_t addr, uint32_t* r) {
    asm volatile("ldmatrix.sync.aligned.m8n8.x4.shared.b16 {%0,%1,%2,%3}, [%4];"
                 : "=r"(r[0]), "=r"(r[1]), "=r"(r[2]), "=r"(r[3]) : "r"(addr));
}
__device__ __forceinline__ void mma16816(float* d, const uint32_t* a, const uint32_t* b) {
    asm volatile(
        "mma.sync.aligned.m16n8k16.row.col.f32.f16.f16.f32 "
        "{%0,%1,%2,%3}, {%4,%5,%6,%7}, {%8,%9}, {%0,%1,%2,%3};"
        : "+f"(d[0]), "+f"(d[1]), "+f"(d[2]), "+f"(d[3])
        : "r"(a[0]), "r"(a[1]), "r"(a[2]), "r"(a[3]), "r"(b[0]), "r"(b[1]));
}

// ---------------- conversion kernels ----------------
// A -> fp16 hi + fp16 residual (captures A to ~2^-23)
__global__ __launch_bounds__(256) void convA(const float* __restrict__ A) {
    int idx = (blockIdx.x * 256 + threadIdx.x) * 4;
    float4 v = *(const float4*)(A + idx);
    __half h[4], l[4];
    float x[4] = {v.x, v.y, v.z, v.w};
    #pragma unroll
    for (int i = 0; i < 4; i++) {
        h[i] = __float2half_rn(x[i]);
        l[i] = __float2half_rn(x[i] - __half2float(h[i]));
    }
    *(uint2*)(g_ahi + idx) = *(uint2*)h;
    *(uint2*)(g_alo + idx) = *(uint2*)l;
}

// transpose W [K x N] -> fp16 [N x K]
__global__ __launch_bounds__(256) void convW(const float* __restrict__ W0,
                                             const float* __restrict__ W1,
                                             const float* __restrict__ W2) {
    __shared__ float ts[32][33];
    const int mat = blockIdx.z;
    const float* Wm = (mat == 0) ? W0 : (mat == 1) ? W1 : W2;
    const int n0 = blockIdx.x * 32, k0 = blockIdx.y * 32;
    const int tx = threadIdx.x & 31, ty = threadIdx.x >> 5;  // 32 x 8
    #pragma unroll
    for (int i = 0; i < 4; i++)
        ts[ty + i * 8][tx] = Wm[(size_t)(k0 + ty + i * 8) * HID + n0 + tx];
    __syncthreads();
    size_t base = (size_t)mat * 2359296;
    #pragma unroll
    for (int i = 0; i < 4; i++) {
        int n = n0 + ty + i * 8, k = k0 + tx;
        g_wf[base + (size_t)n * HID + k] = __float2half_rn(ts[tx][ty + i * 8]);
    }
}

// ---------------- HMMA fp16 2-pass GEMM (128x64 tile, 2 CTA/SM) ------------
__device__ __forceinline__ void load_chunk(
    uint32_t sbase, const __half* Ah, const __half* Al,
    const __half* Bf, int t, int tid)
{
    const int kof = t * BK;
    #pragma unroll
    for (int i = 0; i < 4; i++) {           // A: 128 rows x 8 x 16B
        int l = tid + i * 256;
        int row = l >> 3, c16 = l & 7;
        uint32_t so = SWZ128((uint32_t)(row * 128 + c16 * 16));
        size_t go = (size_t)row * HID + kof + c16 * 8;
        CP_ASYNC16(sbase + so,         Ah + go);
        CP_ASYNC16(sbase + 16384 + so, Al + go);
    }
    #pragma unroll
    for (int i = 0; i < 2; i++) {           // B: 64 rows x 8 x 16B
        int l = tid + i * 256;
        int row = l >> 3, c16 = l & 7;
        uint32_t so = SWZ128((uint32_t)(row * 128 + c16 * 16));
        size_t go = (size_t)row * HID + kof + c16 * 8;
        CP_ASYNC16(sbase + 32768 + so, Bf + go);
    }
}

__global__ __launch_bounds__(256, 2) void qkv_mma() {
    extern __shared__ char smem[];
    const uint32_t sb = smem_u32(smem);
    const int tid = threadIdx.x, wid = tid >> 5, lid = tid & 31;
    const int wm = wid >> 1, wn = wid & 1;           // 4m x 2n, warp tile 32x32
    const int nt = blockIdx.x, mt = blockIdx.y, mat = blockIdx.z;

    const __half* Ah = g_ahi + (size_t)mt * BM * HID;
    const __half* Al = g_alo + (size_t)mt * BM * HID;
    const __half* Bf = g_wf + (size_t)mat * 2359296 + (size_t)nt * BN * HID;
    float* O = (mat == 0) ? g_q : (mat == 1) ? g_k : g_v;

    float acc[2][4][4];
    #pragma unroll
    for (int i = 0; i < 2; i++)
        #pragma unroll
        for (int j = 0; j < 4; j++)
            #pragma unroll
            for (int r = 0; r < 4; r++) acc[i][j][r] = 0.f;

    const int q = lid >> 3, r8 = lid & 7;
    const int a_row = wm * 32 + ((q & 1) << 3) + r8;
    const int a_kb  = (q >> 1) << 4;
    const int b_rowbase = wn * 32 + ((q >> 1) << 3) + r8;
    const int b_kb  = (q & 1) << 4;

    load_chunk(sb, Ah, Al, Bf, 0, tid); CP_COMMIT();

    for (int t = 0; t < NCHUNK; ++t) {
        CP_WAIT0();
        __syncthreads();
        if (t + 1 < NCHUNK) {
            load_chunk(sb + ((t + 1) & 1) * STG_BYTES, Ah, Al, Bf, t + 1, tid);
            CP_COMMIT();
        }
        const uint32_t stg = sb + (t & 1) * STG_BYTES;

        #pragma unroll
        for (int ks = 0; ks < 4; ++ks) {
            uint32_t ahi[2][4], alo[2][4];
            #pragma unroll
            for (int i = 0; i < 2; i++) {
                uint32_t off = SWZ128((uint32_t)((a_row + i * 16) * 128 + ks * 32 + a_kb));
                ldsm4(stg + off,         ahi[i]);
                ldsm4(stg + 16384 + off, alo[i]);
            }
            #pragma unroll
            for (int p = 0; p < 2; p++) {
                uint32_t bh[4];
                uint32_t off = SWZ128((uint32_t)((b_rowbase + p * 16) * 128 + ks * 32 + b_kb));
                ldsm4(stg + 32768 + off, bh);
                #pragma unroll
                for (int i = 0; i < 2; i++) {
                    mma16816(acc[i][2 * p],     ahi[i], bh);
                    mma16816(acc[i][2 * p],     alo[i], bh);
                    mma16816(acc[i][2 * p + 1], ahi[i], bh + 2);
                    mma16816(acc[i][2 * p + 1], alo[i], bh + 2);
                }
            }
        }
    }

    const int orow0 = mt * BM + wm * 32 + (lid >> 2);
    const int ocol0 = nt * BN + wn * 32 + (lid & 3) * 2;
    #pragma unroll
    for (int i = 0; i < 2; i++) {
        #pragma unroll
        for (int j = 0; j < 4; j++) {
            float* p0 = O + (size_t)(orow0 + i * 16)     * HID + ocol0 + j * 8;
            float* p1 = O + (size_t)(orow0 + i * 16 + 8) * HID + ocol0 + j * 8;
            *(float2*)p0 = make_float2(acc[i][j][0], acc[i][j][1]);
            *(float2*)p1 = make_float2(acc[i][j][2], acc[i][j][3]);
        }
    }
}

// ---------------- sin embedding (fast intrinsics + cached inv table) -------
__global__ void sinemb_kernel(const float* __restrict__ wpos) {
    __shared__ float invs[768];
    const int f = blockIdx.y;
    const int n = blockIdx.x * 256 + threadIdx.x;
    const float linc = 9.210340371976184f / 767.0f;
    for (int i = threadIdx.x; i < 768; i += 256)
        invs[i] = __expf(-linc * (float)i);
    __syncthreads();
    const float p = (float)(MAXPAST - f);
    float acc = 0.f;
    for (int i = 0; i < 768; i++) {
        float s, c;
        __sincosf(p * invs[i], &s, &c);
        acc += s * wpos[(size_t)i * HID + n];
        acc += c * wpos[(size_t)(i + 768) * HID + n];
    }
    g_sin[f * HID + n] = acc;
}

// ---------------- attention (round-13 best version) ----------------
__global__ __launch_bounds__(256) void attn_kernel(
    const unsigned char* __restrict__ mask,
    const float* __restrict__ pds,
    float* __restrict__ out, int T)
{
    __shared__ float qs[WW * HD];
    __shared__ float ks[CC * KSTR];
    __shared__ float vs[CC * HD];
    __shared__ float lg[WW * CC];
    __shared__ float ssc[HD];
    __shared__ int   sval[CC];

    const int u = blockIdx.x, h = blockIdx.y, b = blockIdx.z;
    const int tid = threadIdx.x;

    if (tid < HD) {
        const float qsc = 0.0721687836487032f / 0.693147180559945f;
        ssc[tid] = qsc * log1pf(expf(pds[tid]));
    }
    if (tid < CC) {
        int tk = u * WW + tid - MAXPAST;
        sval[tid] = (tk >= 0 && tk < T && mask[(size_t)b * T + tk] == 0);
    }
    __syncthreads();

    for (int i = tid; i < WW * (HD / 4); i += 256) {
        int w = i / (HD / 4), dd = i - w * (HD / 4);
        int t = u * WW + w;
        float4 v = make_float4(0.f, 0.f, 0.f, 0.f);
        if (t < T) {
            float4 r = *(const float4*)&g_q[((size_t)b * T + t) * HID + h * HD + dd * 4];
            v = make_float4(r.x * ssc[dd * 4], r.y * ssc[dd * 4 + 1],
                            r.z * ssc[dd * 4 + 2], r.w * ssc[dd * 4 + 3]);
        }
        *(float4*)&qs[w * HD + dd * 4] = v;
    }
    for (int i = tid; i < CC * (HD / 4); i += 256) {
        int c = i / (HD / 4), dd = i - c * (HD / 4);
        int t = u * WW + c - MAXPAST;
        float4 kv = make_float4(0.f, 0.f, 0.f, 0.f);
        float4 vv = make_float4(0.f, 0.f, 0.f, 0.f);
        if (t >= 0 && t < T) {
            size_t off = ((size_t)b * T + t) * HID + h * HD + dd * 4;
            kv = *(const float4*)&g_k[off];
            vv = *(const float4*)&g_v[off];
        }
        *(float4*)&ks[c * KSTR + dd * 4] = kv;
        *(float4*)&vs[c * HD + dd * 4]  = vv;
    }
    __syncthreads();

    for (int idx = tid; idx < WW * CC; idx += 256) {
        int w = idx / CC, c = idx - w * CC;
        const float4* qp = (const float4*)(qs + w * HD);
        const float4* kp = (const float4*)(ks + c * KSTR);
        float4 a4 = make_float4(0.f, 0.f, 0.f, 0.f);
        #pragma unroll 8
        for (int d = 0; d < HD / 4; d++) {
            float4 qv = qp[d], kv = kp[d];
            a4.x = fmaf(qv.x, kv.x, a4.x);
            a4.y = fmaf(qv.y, kv.y, a4.y);
            a4.z = fmaf(qv.z, kv.z, a4.z);
            a4.w = fmaf(qv.w, kv.w, a4.w);
        }
        lg[idx] = (a4.x + a4.y) + (a4.z + a4.w);
    }
    __syncthreads();

    for (int idx = tid; idx < WW * FF; idx += 256) {
        int w = idx / FF, f = idx - w * FF;
        const float4* qp = (const float4*)(qs + w * HD);
        const float4* sp = (const float4*)(g_sin + (size_t)f * HID + h * HD);
        float4 a4 = make_float4(0.f, 0.f, 0.f, 0.f);
        #pragma unroll 8
        for (int d = 0; d < HD / 4; d++) {
            float4 qv = qp[d], sv = sp[d];
            a4.x = fmaf(qv.x, sv.x, a4.x);
            a4.y = fmaf(qv.y, sv.y, a4.y);
            a4.z = fmaf(qv.z, sv.z, a4.z);
            a4.w = fmaf(qv.w, sv.w, a4.w);
        }
        lg[w * CC + w + f] += (a4.x + a4.y) + (a4.z + a4.w);
    }
    __syncthreads();

    for (int idx = tid; idx < WW * CC; idx += 256) {
        int w = idx / CC, c = idx - w * CC;
        float lv = tanhf(lg[idx] * (1.f / 50.f)) * 50.f;
        bool ok = sval[c] && (c >= w) && (c <= w + MAXPAST);
        lg[idx] = ok ? lv : -FLT_MAX;
    }
    __syncthreads();

    if (tid < WW) {
        const int w = tid;
        float row[CC];
        float mx = -FLT_MAX;
        #pragma unroll
        for (int c = 0; c < CC; c++) {
            row[c] = lg[w * CC + c];
            if (row[c] > mx) mx = row[c];
        }
        float s = 0.f;
        #pragma unroll
        for (int c = 0; c < CC; c++) {
            float e = (row[c] == -FLT_MAX) ? 0.f : expf(row[c] - mx);
            row[c] = e; s += e;
        }
        float inv = 1.f / s;
        #pragma unroll
        for (int c = 0; c < CC; c++) lg[w * CC + c] = row[c] * inv;
    }
    __syncthreads();

    for (int i = tid; i < WW * (HD / 4); i += 256) {
        int w = i / (HD / 4), dd = i - w * (HD / 4);
        int t = u * WW + w;
        if (t < T) {
            const float* pp = lg + w * CC;
            float4 a = make_float4(0.f, 0.f, 0.f, 0.f);
            #pragma unroll
            for (int c = 0; c < CC; c++) {
                float p = pp[c];
                const float* vp = &vs[c * HD + dd * 4];
                a.x = fmaf(p, vp[0], a.x);
                a.y = fmaf(p, vp[1], a.y);
                a.z = fmaf(p, vp[2], a.z);
                a.w = fmaf(p, vp[3], a.w);
            }
            *(float4*)&out[((size_t)b * T + t) * HID + h * HD + dd * 4] = a;
        }
    }
}

// ---------------------------------------------------------------------------
extern "C" void kernel_launch(void* const* d_in, const int* in_sizes, int n_in,
                              void* d_out, int out_size)
{
    const float*         hs   = (const float*)d_in[0];
    const unsigned char* mask = (const unsigned char*)d_in[1];
    const float*         wq   = (const float*)d_in[2];
    const float*         wk   = (const float*)d_in[3];
    const float*         wv   = (const float*)d_in[4];
    const float*         wpos = (const float*)d_in[5];
    const float*         pds  = (const float*)d_in[6];

    const int M  = in_sizes[0] / HID;   // 16384
    const int T  = 4096;
    const int Bq = M / T;
    const int U  = (T + WW - 1) / WW;   // 342

    static int smem_set = 0;
    const int dynsmem = NSTAGE * STG_BYTES;  // 81920
    if (!smem_set) {
        cudaFuncSetAttribute(qkv_mma, cudaFuncAttributeMaxDynamicSharedMemorySize, dynsmem);
        smem_set = 1;
    }

    convA<<<M * HID / 1024, 256>>>(hs);
    convW<<<dim3(HID / 32, HID / 32, 3), 256>>>(wq, wk, wv);
    sinemb_kernel<<<dim3(HID / 256, FF), 256>>>(wpos);
    qkv_mma<<<dim3(HID / BN, M / BM, 3), 256, dynsmem>>>();
    attn_kernel<<<dim3(U, NH, Bq), 256>>>(mask, pds, (float*)d_out, T);
}